// round 12
// baseline (speedup 1.0000x reference)
#include <cuda_runtime.h>
#include <cuda_fp16.h>
#include <cstdint>

// ============================================================================
// SelfAttention via mma.sync (HMMA) fp16 hi/lo-split GEMMs.
// R12: R10 numerics (3-pass f32-acc stages 1/2/4, 1-pass stage 6) +
//      fragment double-buffering: LDSM block for ks+1 issued BEFORE the MMA
//      block for ks, so LDSM latency/crossbar time hides under MMA issue.
// B=4, L=2048, D=1024.
// ============================================================================

#define BATCH 4
#define LSEQ  2048
#define DDIM  1024

#define BM 128
#define BN 128
#define BK 32

// ---- scratch ---------------------------------------------------------------
__device__ __half g_xh[8388608],  g_xl[8388608];
__device__ __half g_w1h[1048576], g_w1l[1048576];
__device__ __half g_w2h[1048576], g_w2l[1048576];
__device__ __half g_qh[8388608],  g_ql[8388608];
__device__ __half g_vh[8388608],  g_vl[8388608];
__device__ __half g_vth[8388608];                 // V^T hi only (stage-6 1-pass)
__device__ float  g_S[16777216];
__device__ __half g_ph[16777216];                  // softmax P (fp16)

// ---- helpers ---------------------------------------------------------------
__device__ __forceinline__ uint32_t smem_u32(const void* p) {
    uint32_t a;
    asm("{ .reg .u64 t; cvta.to.shared.u64 t, %1; cvt.u32.u64 %0, t; }" : "=r"(a) : "l"(p));
    return a;
}
__device__ __forceinline__ void cp16(uint32_t dst, const void* src) {
    asm volatile("cp.async.cg.shared.global [%0], [%1], 16;" :: "r"(dst), "l"(src));
}
__device__ __forceinline__ void cp_commit() { asm volatile("cp.async.commit_group;" ::: "memory"); }
#define CP_WAIT1 asm volatile("cp.async.wait_group 1;" ::: "memory")
#define CP_WAIT0 asm volatile("cp.async.wait_group 0;" ::: "memory")

__device__ __forceinline__ void ldsm4(uint32_t& r0, uint32_t& r1, uint32_t& r2, uint32_t& r3,
                                      uint32_t addr) {
    asm volatile("ldmatrix.sync.aligned.m8n8.x4.shared.b16 {%0,%1,%2,%3}, [%4];"
                 : "=r"(r0), "=r"(r1), "=r"(r2), "=r"(r3) : "r"(addr));
}
__device__ __forceinline__ void mma16816(float* c, const uint32_t* a, const uint32_t* b) {
    asm volatile(
        "mma.sync.aligned.m16n8k16.row.col.f32.f16.f16.f32 "
        "{%0,%1,%2,%3}, {%4,%5,%6,%7}, {%8,%9}, {%0,%1,%2,%3};"
        : "+f"(c[0]), "+f"(c[1]), "+f"(c[2]), "+f"(c[3])
        : "r"(a[0]), "r"(a[1]), "r"(a[2]), "r"(a[3]), "r"(b[0]), "r"(b[1]));
}
__device__ __forceinline__ uint32_t pk2h(float a, float b) {
    __half2 t = __floats2half2_rn(a, b);
    return *reinterpret_cast<uint32_t*>(&t);
}

// SMEM layout (bytes): 4 tiles of 128 rows x 80 B = 10240 B each
#define T_AH 0
#define T_AL 10240
#define T_BH 20480
#define T_BL 30720
#define STAGE 40960
#define SMEM_TOTAL (2 * STAGE)    // 81920

// ============================================================================
// C[M,N] = A[M,K] * B[N,K]^T  (both K-contiguous).
// NPASS=3: hi/lo split, 3 MMA passes, all f32 acc. NPASS=1: plain fp16 1 pass.
// grid (N/BN, M/BM, batch), 256 threads (8 warps, warp tile 64x32).
// Fragment double-buffer: LDSM(ks+1) issued before MMA(ks).
// ============================================================================
template <bool BIAS, bool HOUT, int NPASS>
__global__ __launch_bounds__(256, 1) void gemm_hmma(
    const __half* __restrict__ Ah, const __half* __restrict__ Al,
    const __half* __restrict__ Bh, const __half* __restrict__ Bl,
    const float* __restrict__ bias,
    float* __restrict__ Cf, __half* __restrict__ Ch, __half* __restrict__ Cl,
    int K, int lda, int ldb, int ldc,
    long long sA, long long sB, long long sC)
{
    extern __shared__ char smem[];
    const uint32_t sb = smem_u32(smem);

    const int tid = threadIdx.x, wid = tid >> 5, lane = tid & 31;
    const int wy = wid >> 2, wx = wid & 3;           // warp grid 2 x 4
    const int m0 = blockIdx.y * BM, n0 = blockIdx.x * BN;
    const long long z = blockIdx.z;
    Ah += z * sA; Bh += z * sB;
    if (NPASS == 3) { Al += z * sA; Bl += z * sB; }
    if (HOUT) { Ch += z * sC; Cl += z * sC; } else { Cf += z * sC; }

    // global->smem mapping: 512 16B segs per tile (128 rows x 4)
    const int grow = tid >> 2;
    const int gseg = tid & 3;
    const int lr = lane & 15, lc = lane >> 4;

    float acc[4][4][4];
#pragma unroll
    for (int i = 0; i < 4; ++i)
#pragma unroll
        for (int j = 0; j < 4; ++j)
#pragma unroll
            for (int e = 0; e < 4; ++e) acc[i][j][e] = 0.f;

    // double-buffered fragments
    uint32_t ahf[2][4][4], alf[2][4][4], bhf[2][4][2], blf[2][4][2];

    const int nk = K / BK;

    auto load_chunk = [&](int t, int b) {
        const uint32_t st = sb + b * STAGE;
        const int k0 = t * BK;
#pragma unroll
        for (int h = 0; h < 2; ++h) {
            const int row = grow + h * 64;
            const uint32_t d = (uint32_t)(row * 80 + gseg * 16);
            const size_t ga = (size_t)(m0 + row) * lda + k0 + gseg * 8;
            const size_t gb = (size_t)(n0 + row) * ldb + k0 + gseg * 8;
            cp16(st + T_AH + d, Ah + ga);
            cp16(st + T_BH + d, Bh + gb);
            if (NPASS == 3) {
                cp16(st + T_AL + d, Al + ga);
                cp16(st + T_BL + d, Bl + gb);
            }
        }
    };

    // LDSM all fragments for k-step `ks` of current smem chunk into buffer fb
    auto ldfr = [&](int ks, int fb, uint32_t st) {
        const uint32_t acol = (uint32_t)(ks * 32 + lc * 16);
        const uint32_t ab = st + T_AH + (uint32_t)((wy * 64 + lr) * 80) + acol;
        const uint32_t bb = st + T_BH + (uint32_t)((wx * 32 + lr) * 80) + acol;
#pragma unroll
        for (int i = 0; i < 4; ++i) {
            const uint32_t ad = ab + (uint32_t)(i * 16 * 80);
            ldsm4(ahf[fb][i][0], ahf[fb][i][1], ahf[fb][i][2], ahf[fb][i][3], ad);
            if (NPASS == 3)
                ldsm4(alf[fb][i][0], alf[fb][i][1], alf[fb][i][2], alf[fb][i][3],
                      ad + (T_AL - T_AH));
        }
#pragma unroll
        for (int j = 0; j < 2; ++j) {
            const uint32_t bd = bb + (uint32_t)(j * 16 * 80);
            uint32_t r0, r1, r2, r3;
            ldsm4(r0, r1, r2, r3, bd);
            bhf[fb][2*j][0] = r0; bhf[fb][2*j][1] = r2;
            bhf[fb][2*j+1][0] = r1; bhf[fb][2*j+1][1] = r3;
            if (NPASS == 3) {
                ldsm4(r0, r1, r2, r3, bd + (T_BL - T_BH));
                blf[fb][2*j][0] = r0; blf[fb][2*j][1] = r2;
                blf[fb][2*j+1][0] = r1; blf[fb][2*j+1][1] = r3;
            }
        }
    };

    auto do_mma = [&](int fb) {
#pragma unroll
        for (int i = 0; i < 4; ++i)
#pragma unroll
            for (int j = 0; j < 4; ++j)
                mma16816(acc[i][j], ahf[fb][i], bhf[fb][j]);
        if (NPASS == 3) {
#pragma unroll
            for (int i = 0; i < 4; ++i)
#pragma unroll
                for (int j = 0; j < 4; ++j)
                    mma16816(acc[i][j], ahf[fb][i], blf[fb][j]);
#pragma unroll
            for (int i = 0; i < 4; ++i)
#pragma unroll
                for (int j = 0; j < 4; ++j)
                    mma16816(acc[i][j], alf[fb][i], bhf[fb][j]);
        }
    };

    load_chunk(0, 0);
    cp_commit();

    for (int t = 0; t < nk; ++t) {
        const int buf = t & 1;
        if (t + 1 < nk) { load_chunk(t + 1, buf ^ 1); cp_commit(); CP_WAIT1; }
        else            { CP_WAIT0; }
        __syncthreads();

        const uint32_t st = sb + buf * STAGE;
        // pipeline: both LDSM blocks issued up front; MMA(ks0) only depends on
        // the first block, MMA(ks1) runs while nothing else is outstanding.
        ldfr(0, 0, st);
        ldfr(1, 1, st);
        do_mma(0);
        do_mma(1);
        __syncthreads();
    }

    // ---- epilogue ----
    const int rbase = m0 + wy * 64 + (lane >> 2);
    const int cbase = n0 + wx * 32 + (lane & 3) * 2;
#pragma unroll
    for (int j = 0; j < 4; ++j) {
        const int col = cbase + j * 8;
        float b0 = 0.f, b1 = 0.f;
        if (BIAS) { b0 = __ldg(&bias[col]); b1 = __ldg(&bias[col + 1]); }
#pragma unroll
        for (int i = 0; i < 4; ++i) {
            const int row = rbase + i * 16;
            float v0 = acc[i][j][0] + b0, v1 = acc[i][j][1] + b1;
            float v2 = acc[i][j][2] + b0, v3 = acc[i][j][3] + b1;
            if (HOUT) {
                float h0 = __half2float(__float2half_rn(v0));
                float h1 = __half2float(__float2half_rn(v1));
                float h2 = __half2float(__float2half_rn(v2));
                float h3 = __half2float(__float2half_rn(v3));
                *reinterpret_cast<uint32_t*>(&Ch[(size_t)row * ldc + col])       = pk2h(v0, v1);
                *reinterpret_cast<uint32_t*>(&Ch[(size_t)(row + 8) * ldc + col]) = pk2h(v2, v3);
                *reinterpret_cast<uint32_t*>(&Cl[(size_t)row * ldc + col])       = pk2h(v0 - h0, v1 - h1);
                *reinterpret_cast<uint32_t*>(&Cl[(size_t)(row + 8) * ldc + col]) = pk2h(v2 - h2, v3 - h3);
            } else {
                *reinterpret_cast<float2*>(&Cf[(size_t)row * ldc + col])       = make_float2(v0, v1);
                *reinterpret_cast<float2*>(&Cf[(size_t)(row + 8) * ldc + col]) = make_float2(v2, v3);
            }
        }
    }
}

// ---------------------------------------------------------------------------
// fp32 -> fp16 hi/lo split
// ---------------------------------------------------------------------------
__global__ void split_kernel(const float4* __restrict__ in,
                             uint2* __restrict__ hi, uint2* __restrict__ lo, int n4)
{
    for (int i = blockIdx.x * blockDim.x + threadIdx.x; i < n4; i += gridDim.x * blockDim.x) {
        float4 v = in[i];
        float h0 = __half2float(__float2half_rn(v.x));
        float h1 = __half2float(__float2half_rn(v.y));
        float h2 = __half2float(__float2half_rn(v.z));
        float h3 = __half2float(__float2half_rn(v.w));
        hi[i] = make_uint2(pk2h(v.x, v.y), pk2h(v.z, v.w));
        lo[i] = make_uint2(pk2h(v.x - h0, v.y - h1), pk2h(v.z - h2, v.w - h3));
    }
}

// ---------------------------------------------------------------------------
// V[L,D] -> Vt[D,L] (hi only), per batch
// ---------------------------------------------------------------------------
__global__ void transpose_h(const __half* __restrict__ hi, __half* __restrict__ thi)
{
    __shared__ __half sm[32][33];
    const size_t zi = (size_t)blockIdx.z * LSEQ * DDIM;
    const int d0 = blockIdx.x * 32, l0 = blockIdx.y * 32;
    const int tx = threadIdx.x, ty = threadIdx.y;

#pragma unroll
    for (int i = 0; i < 4; ++i)
        sm[ty + 8*i][tx] = hi[zi + (size_t)(l0 + ty + 8*i) * DDIM + d0 + tx];
    __syncthreads();
#pragma unroll
    for (int i = 0; i < 4; ++i)
        thi[zi + (size_t)(d0 + ty + 8*i) * LSEQ + l0 + tx] = sm[tx][ty + 8*i];
}

// ---------------------------------------------------------------------------
// Row softmax (2048 wide) -> P fp16
// ---------------------------------------------------------------------------
__global__ __launch_bounds__(256) void softmax_rows(const float* __restrict__ S,
                                                    __half* __restrict__ Ph)
{
    const size_t row = blockIdx.x;
    const float* p = S + row * (size_t)LSEQ;
    const int tid = threadIdx.x;

    float4 v0 = ((const float4*)p)[tid];
    float4 v1 = ((const float4*)p)[tid + 256];

    __shared__ float red[32];
    const int lane = tid & 31, warp = tid >> 5;

    float m = fmaxf(fmaxf(fmaxf(v0.x, v0.y), fmaxf(v0.z, v0.w)),
                    fmaxf(fmaxf(v1.x, v1.y), fmaxf(v1.z, v1.w)));
#pragma unroll
    for (int o = 16; o > 0; o >>= 1) m = fmaxf(m, __shfl_xor_sync(0xffffffffu, m, o));
    if (lane == 0) red[warp] = m;
    __syncthreads();
    if (warp == 0) {
        float mm = (lane < 8) ? red[lane] : -3.4e38f;
#pragma unroll
        for (int o = 4; o > 0; o >>= 1) mm = fmaxf(mm, __shfl_xor_sync(0xffffffffu, mm, o));
        if (lane == 0) red[0] = mm;
    }
    __syncthreads();
    m = red[0];
    __syncthreads();

    v0.x = __expf(v0.x - m); v0.y = __expf(v0.y - m);
    v0.z = __expf(v0.z - m); v0.w = __expf(v0.w - m);
    v1.x = __expf(v1.x - m); v1.y = __expf(v1.y - m);
    v1.z = __expf(v1.z - m); v1.w = __expf(v1.w - m);
    float s = v0.x + v0.y + v0.z + v0.w + v1.x + v1.y + v1.z + v1.w;
#pragma unroll
    for (int o = 16; o > 0; o >>= 1) s += __shfl_xor_sync(0xffffffffu, s, o);
    if (lane == 0) red[warp] = s;
    __syncthreads();
    if (warp == 0) {
        float ss = (lane < 8) ? red[lane] : 0.f;
#pragma unroll
        for (int o = 4; o > 0; o >>= 1) ss += __shfl_xor_sync(0xffffffffu, ss, o);
        if (lane == 0) red[0] = ss;
    }
    __syncthreads();
    const float inv = 1.0f / red[0];

    float a[8] = {v0.x*inv, v0.y*inv, v0.z*inv, v0.w*inv, v1.x*inv, v1.y*inv, v1.z*inv, v1.w*inv};
    const size_t o0 = row * (size_t)LSEQ + tid * 4;
    const size_t o1 = row * (size_t)LSEQ + (tid + 256) * 4;
    *reinterpret_cast<uint2*>(&Ph[o0]) = make_uint2(pk2h(a[0], a[1]), pk2h(a[2], a[3]));
    *reinterpret_cast<uint2*>(&Ph[o1]) = make_uint2(pk2h(a[4], a[5]), pk2h(a[6], a[7]));
}

// ---------------------------------------------------------------------------
extern "C" void kernel_launch(void* const* d_in, const int* in_sizes, int n_in,
                              void* d_out, int out_size)
{
    const float* x  = (const float*)d_in[0];
    const float* W1 = (const float*)d_in[1];
    const float* b1 = (const float*)d_in[2];
    const float* W2 = (const float*)d_in[3];
    const float* b2 = (const float*)d_in[4];
    float* out = (float*)d_out;

    __half *xh, *xl, *w1h, *w1l, *w2h, *w2l, *qh, *ql, *vh, *vl, *vth, *phh;
    float* S;
    cudaGetSymbolAddress((void**)&xh, g_xh);   cudaGetSymbolAddress((void**)&xl, g_xl);
    cudaGetSymbolAddress((void**)&w1h, g_w1h); cudaGetSymbolAddress((void**)&w1l, g_w1l);
    cudaGetSymbolAddress((void**)&w2h, g_w2h); cudaGetSymbolAddress((void**)&w2l, g_w2l);
    cudaGetSymbolAddress((void**)&qh, g_qh);   cudaGetSymbolAddress((void**)&ql, g_ql);
    cudaGetSymbolAddress((void**)&vh, g_vh);   cudaGetSymbolAddress((void**)&vl, g_vl);
    cudaGetSymbolAddress((void**)&vth, g_vth);
    cudaGetSymbolAddress((void**)&phh, g_ph);
    cudaGetSymbolAddress((void**)&S, g_S);

    cudaFuncSetAttribute(gemm_hmma<true,  true,  3>, cudaFuncAttributeMaxDynamicSharedMemorySize, SMEM_TOTAL);
    cudaFuncSetAttribute(gemm_hmma<false, false, 3>, cudaFuncAttributeMaxDynamicSharedMemorySize, SMEM_TOTAL);
    cudaFuncSetAttribute(gemm_hmma<false, false, 1>, cudaFuncAttributeMaxDynamicSharedMemorySize, SMEM_TOTAL);

    const long long LD = (long long)LSEQ * DDIM;
    const long long LL = (long long)LSEQ * LSEQ;

    // 1. split fp32 -> fp16 hi/lo
    split_kernel<<<4096, 256>>>((const float4*)x,  (uint2*)xh,  (uint2*)xl,  8388608 / 4);
    split_kernel<<<1024, 256>>>((const float4*)W1, (uint2*)w1h, (uint2*)w1l, 1048576 / 4);
    split_kernel<<<1024, 256>>>((const float4*)W2, (uint2*)w2h, (uint2*)w2l, 1048576 / 4);

    // 2. Q = x@W1^T + b1 ; V = x@W2^T + b2  (M=8192, N=1024, K=1024, 3-pass)
    {
        dim3 g(DDIM / BN, (BATCH * LSEQ) / BM, 1);
        gemm_hmma<true, true, 3><<<g, 256, SMEM_TOTAL>>>(
            xh, xl, w1h, w1l, b1, nullptr, qh, ql, DDIM, DDIM, DDIM, DDIM, 0, 0, 0);
        gemm_hmma<true, true, 3><<<g, 256, SMEM_TOTAL>>>(
            xh, xl, w2h, w2l, b2, nullptr, vh, vl, DDIM, DDIM, DDIM, DDIM, 0, 0, 0);
    }

    // 3. Vt = V^T per batch (hi only, for 1-pass stage 6)
    transpose_h<<<dim3(DDIM / 32, LSEQ / 32, BATCH), dim3(32, 8)>>>(vh, vth);

    // 4. S[b] = Q[b] @ V[b]^T  (M=2048, N=2048, K=1024, 3-pass)
    {
        dim3 g(LSEQ / BN, LSEQ / BM, BATCH);
        gemm_hmma<false, false, 3><<<g, 256, SMEM_TOTAL>>>(
            qh, ql, vh, vl, nullptr, S, nullptr, nullptr, DDIM, DDIM, DDIM, LSEQ, LD, LD, LL);
    }

    // 5. softmax -> P fp16
    softmax_rows<<<BATCH * LSEQ, 256>>>(S, phh);

    // 6. out[b] = P[b] @ Vt[b]^T  (M=2048, N=1024, K=2048, 1-pass fp16)
    {
        dim3 g(DDIM / BN, LSEQ / BM, BATCH);
        gemm_hmma<false, false, 1><<<g, 256, SMEM_TOTAL>>>(
            phh, phh, vth, vth, nullptr, out, nullptr, nullptr, LSEQ, LSEQ, LSEQ, DDIM, LL, LD, LD);
    }
}

// round 17
// speedup vs baseline: 1.1406x; 1.1406x over previous
#include <cuda_runtime.h>
#include <cuda_fp16.h>
#include <cstdint>

// ============================================================================
// SelfAttention via mma.sync (HMMA) fp16 hi/lo-split GEMMs.
// R13: R10 numerics + PERSISTENT CTAs (grid=2*148, grid-stride tile loop) to
//      kill wave-quantization tails, + stages 1/2 merged into one dual-output
//      launch. Inner loop identical to R10 (best measured: 43% tensor).
// B=4, L=2048, D=1024.
// ============================================================================

#define BATCH 4
#define LSEQ  2048
#define DDIM  1024

#define BM 128
#define BN 128
#define BK 32
#define NPERSIST 296      // 2 CTAs x 148 SMs

// ---- scratch ---------------------------------------------------------------
__device__ __half g_xh[8388608],  g_xl[8388608];
__device__ __half g_w1h[1048576], g_w1l[1048576];
__device__ __half g_w2h[1048576], g_w2l[1048576];
__device__ __half g_qh[8388608],  g_ql[8388608];
__device__ __half g_vh[8388608],  g_vl[8388608];
__device__ __half g_vth[8388608];                 // V^T hi only (stage-6 1-pass)
__device__ float  g_S[16777216];
__device__ __half g_ph[16777216];                  // softmax P (fp16)

// ---- helpers ---------------------------------------------------------------
__device__ __forceinline__ uint32_t smem_u32(const void* p) {
    uint32_t a;
    asm("{ .reg .u64 t; cvta.to.shared.u64 t, %1; cvt.u32.u64 %0, t; }" : "=r"(a) : "l"(p));
    return a;
}
__device__ __forceinline__ void cp16(uint32_t dst, const void* src) {
    asm volatile("cp.async.cg.shared.global [%0], [%1], 16;" :: "r"(dst), "l"(src));
}
__device__ __forceinline__ void cp_commit() { asm volatile("cp.async.commit_group;" ::: "memory"); }
#define CP_WAIT1 asm volatile("cp.async.wait_group 1;" ::: "memory")
#define CP_WAIT0 asm volatile("cp.async.wait_group 0;" ::: "memory")

__device__ __forceinline__ void ldsm4(uint32_t& r0, uint32_t& r1, uint32_t& r2, uint32_t& r3,
                                      uint32_t addr) {
    asm volatile("ldmatrix.sync.aligned.m8n8.x4.shared.b16 {%0,%1,%2,%3}, [%4];"
                 : "=r"(r0), "=r"(r1), "=r"(r2), "=r"(r3) : "r"(addr));
}
__device__ __forceinline__ void mma16816(float* c, const uint32_t* a, const uint32_t* b) {
    asm volatile(
        "mma.sync.aligned.m16n8k16.row.col.f32.f16.f16.f32 "
        "{%0,%1,%2,%3}, {%4,%5,%6,%7}, {%8,%9}, {%0,%1,%2,%3};"
        : "+f"(c[0]), "+f"(c[1]), "+f"(c[2]), "+f"(c[3])
        : "r"(a[0]), "r"(a[1]), "r"(a[2]), "r"(a[3]), "r"(b[0]), "r"(b[1]));
}
__device__ __forceinline__ uint32_t pk2h(float a, float b) {
    __half2 t = __floats2half2_rn(a, b);
    return *reinterpret_cast<uint32_t*>(&t);
}

// SMEM layout (bytes): 4 tiles of 128 rows x 80 B = 10240 B each
#define T_AH 0
#define T_AL 10240
#define T_BH 20480
#define T_BL 30720
#define STAGE 40960
#define SMEM_TOTAL (2 * STAGE)    // 81920

// ============================================================================
// Persistent GEMM: C[M,N] = A[M,K] * B[N,K]^T (K-contiguous operands).
// DUAL=1: two B/bias/C sets share the same A (projection Q and V in one
// launch). NPASS=3: hi/lo 3-pass f32-acc; NPASS=1: plain fp16 1-pass.
// grid = NPERSIST CTAs, each grid-strides over tiles.
// Tile space: sel(0/1 if DUAL) x z(nz) x mt x nt.
// ============================================================================
template <bool BIAS, bool HOUT, int NPASS, bool DUAL>
__global__ __launch_bounds__(256, 2) void gemm_persist(
    const __half* __restrict__ Ah, const __half* __restrict__ Al,
    const __half* __restrict__ Bh0, const __half* __restrict__ Bl0,
    const __half* __restrict__ Bh1, const __half* __restrict__ Bl1,
    const float* __restrict__ bias0, const float* __restrict__ bias1,
    float* __restrict__ Cf0, __half* __restrict__ Ch0, __half* __restrict__ Cl0,
    __half* __restrict__ Ch1, __half* __restrict__ Cl1,
    int K, int lda, int ldb, int ldc,
    long long sA, long long sB, long long sC,
    int mt, int nt, int nz)
{
    extern __shared__ char smem[];
    const uint32_t sb = smem_u32(smem);

    const int tid = threadIdx.x, wid = tid >> 5, lane = tid & 31;
    const int wy = wid >> 2, wx = wid & 3;           // warp grid 2 x 4
    const int grow = tid >> 2;
    const int gseg = tid & 3;
    const int lr = lane & 15, lc = lane >> 4;
    const int nk = K / BK;

    const int tiles_one = mt * nt * nz;
    const int tiles_all = DUAL ? 2 * tiles_one : tiles_one;

    for (int tile = blockIdx.x; tile < tiles_all; tile += gridDim.x) {

        int tr = tile, sel = 0;
        if (DUAL && tr >= tiles_one) { sel = 1; tr -= tiles_one; }
        const int z  = tr / (mt * nt);
        const int r  = tr % (mt * nt);
        const int m0 = (r / nt) * BM;
        const int n0 = (r % nt) * BN;

        const __half* pAh = Ah + (long long)z * sA;
        const __half* pAl = Al + (long long)z * sA;
        const __half* pBh = (DUAL && sel) ? Bh1 : Bh0;
        const __half* pBl = (DUAL && sel) ? Bl1 : Bl0;
        pBh += (long long)z * sB;
        if (NPASS == 3) pBl += (long long)z * sB;
        const float* pbias = (DUAL && sel) ? bias1 : bias0;

        float acc[4][4][4];
#pragma unroll
        for (int i = 0; i < 4; ++i)
#pragma unroll
            for (int j = 0; j < 4; ++j)
#pragma unroll
                for (int e = 0; e < 4; ++e) acc[i][j][e] = 0.f;

        auto load_chunk = [&](int t, int b) {
            const uint32_t st = sb + b * STAGE;
            const int k0 = t * BK;
#pragma unroll
            for (int h = 0; h < 2; ++h) {
                const int row = grow + h * 64;
                const uint32_t d = (uint32_t)(row * 80 + gseg * 16);
                const size_t ga = (size_t)(m0 + row) * lda + k0 + gseg * 8;
                const size_t gb = (size_t)(n0 + row) * ldb + k0 + gseg * 8;
                cp16(st + T_AH + d, pAh + ga);
                cp16(st + T_BH + d, pBh + gb);
                if (NPASS == 3) {
                    cp16(st + T_AL + d, pAl + ga);
                    cp16(st + T_BL + d, pBl + gb);
                }
            }
        };

        load_chunk(0, 0);
        cp_commit();

        for (int t = 0; t < nk; ++t) {
            const int buf = t & 1;
            if (t + 1 < nk) { load_chunk(t + 1, buf ^ 1); cp_commit(); CP_WAIT1; }
            else            { CP_WAIT0; }
            __syncthreads();

            const uint32_t st = sb + buf * STAGE;
#pragma unroll
            for (int ks = 0; ks < 2; ++ks) {
                const uint32_t acol = (uint32_t)(ks * 32 + lc * 16);
                const uint32_t ab = st + T_AH + (uint32_t)((wy * 64 + lr) * 80) + acol;
                const uint32_t bb = st + T_BH + (uint32_t)((wx * 32 + lr) * 80) + acol;

                uint32_t ah[4][4], bh[4][2];
#pragma unroll
                for (int i = 0; i < 4; ++i) {
                    const uint32_t ad = ab + (uint32_t)(i * 16 * 80);
                    ldsm4(ah[i][0], ah[i][1], ah[i][2], ah[i][3], ad);
                }
#pragma unroll
                for (int j = 0; j < 2; ++j) {
                    const uint32_t bd = bb + (uint32_t)(j * 16 * 80);
                    uint32_t r0, r1, r2, r3;
                    ldsm4(r0, r1, r2, r3, bd);
                    bh[2*j][0] = r0; bh[2*j][1] = r2;
                    bh[2*j+1][0] = r1; bh[2*j+1][1] = r3;
                }

#pragma unroll
                for (int i = 0; i < 4; ++i)
#pragma unroll
                    for (int j = 0; j < 4; ++j)
                        mma16816(acc[i][j], ah[i], bh[j]);

                if (NPASS == 3) {
                    uint32_t al[4][4], bl[4][2];
#pragma unroll
                    for (int i = 0; i < 4; ++i) {
                        const uint32_t ad = ab + (uint32_t)(i * 16 * 80) + (T_AL - T_AH);
                        ldsm4(al[i][0], al[i][1], al[i][2], al[i][3], ad);
                    }
#pragma unroll
                    for (int j = 0; j < 2; ++j) {
                        const uint32_t bd = bb + (uint32_t)(j * 16 * 80) + (T_BL - T_BH);
                        uint32_t r0, r1, r2, r3;
                        ldsm4(r0, r1, r2, r3, bd);
                        bl[2*j][0] = r0; bl[2*j][1] = r2;
                        bl[2*j+1][0] = r1; bl[2*j+1][1] = r3;
                    }
#pragma unroll
                    for (int i = 0; i < 4; ++i)
#pragma unroll
                        for (int j = 0; j < 4; ++j)
                            mma16816(acc[i][j], ah[i], bl[j]);
#pragma unroll
                    for (int i = 0; i < 4; ++i)
#pragma unroll
                        for (int j = 0; j < 4; ++j)
                            mma16816(acc[i][j], al[i], bh[j]);
                }
            }
            __syncthreads();
        }

        // ---- epilogue (registers only; safe vs next tile's cp.async) ----
        const int rbase = m0 + wy * 64 + (lane >> 2);
        const int cbase = n0 + wx * 32 + (lane & 3) * 2;
#pragma unroll
        for (int j = 0; j < 4; ++j) {
            const int col = cbase + j * 8;
            float b0 = 0.f, b1 = 0.f;
            if (BIAS) { b0 = __ldg(&pbias[col]); b1 = __ldg(&pbias[col + 1]); }
#pragma unroll
            for (int i = 0; i < 4; ++i) {
                const int row = rbase + i * 16;
                float v0 = acc[i][j][0] + b0, v1 = acc[i][j][1] + b1;
                float v2 = acc[i][j][2] + b0, v3 = acc[i][j][3] + b1;
                if (HOUT) {
                    __half* Ch = (DUAL && sel) ? Ch1 : Ch0;
                    __half* Cl = (DUAL && sel) ? Cl1 : Cl0;
                    Ch += (long long)z * sC; Cl += (long long)z * sC;
                    float h0 = __half2float(__float2half_rn(v0));
                    float h1 = __half2float(__float2half_rn(v1));
                    float h2 = __half2float(__float2half_rn(v2));
                    float h3 = __half2float(__float2half_rn(v3));
                    *reinterpret_cast<uint32_t*>(&Ch[(size_t)row * ldc + col])       = pk2h(v0, v1);
                    *reinterpret_cast<uint32_t*>(&Ch[(size_t)(row + 8) * ldc + col]) = pk2h(v2, v3);
                    *reinterpret_cast<uint32_t*>(&Cl[(size_t)row * ldc + col])       = pk2h(v0 - h0, v1 - h1);
                    *reinterpret_cast<uint32_t*>(&Cl[(size_t)(row + 8) * ldc + col]) = pk2h(v2 - h2, v3 - h3);
                } else {
                    float* Cf = Cf0 + (long long)z * sC;
                    *reinterpret_cast<float2*>(&Cf[(size_t)row * ldc + col])       = make_float2(v0, v1);
                    *reinterpret_cast<float2*>(&Cf[(size_t)(row + 8) * ldc + col]) = make_float2(v2, v3);
                }
            }
        }
        __syncthreads();   // all warps done with smem buf1 before next tile's loads
    }
}

// ---------------------------------------------------------------------------
// fp32 -> fp16 hi/lo split
// ---------------------------------------------------------------------------
__global__ void split_kernel(const float4* __restrict__ in,
                             uint2* __restrict__ hi, uint2* __restrict__ lo, int n4)
{
    for (int i = blockIdx.x * blockDim.x + threadIdx.x; i < n4; i += gridDim.x * blockDim.x) {
        float4 v = in[i];
        float h0 = __half2float(__float2half_rn(v.x));
        float h1 = __half2float(__float2half_rn(v.y));
        float h2 = __half2float(__float2half_rn(v.z));
        float h3 = __half2float(__float2half_rn(v.w));
        hi[i] = make_uint2(pk2h(v.x, v.y), pk2h(v.z, v.w));
        lo[i] = make_uint2(pk2h(v.x - h0, v.y - h1), pk2h(v.z - h2, v.w - h3));
    }
}

// ---------------------------------------------------------------------------
// V[L,D] -> Vt[D,L] (hi only), per batch
// ---------------------------------------------------------------------------
__global__ void transpose_h(const __half* __restrict__ hi, __half* __restrict__ thi)
{
    __shared__ __half sm[32][33];
    const size_t zi = (size_t)blockIdx.z * LSEQ * DDIM;
    const int d0 = blockIdx.x * 32, l0 = blockIdx.y * 32;
    const int tx = threadIdx.x, ty = threadIdx.y;

#pragma unroll
    for (int i = 0; i < 4; ++i)
        sm[ty + 8*i][tx] = hi[zi + (size_t)(l0 + ty + 8*i) * DDIM + d0 + tx];
    __syncthreads();
#pragma unroll
    for (int i = 0; i < 4; ++i)
        thi[zi + (size_t)(d0 + ty + 8*i) * LSEQ + l0 + tx] = sm[tx][ty + 8*i];
}

// ---------------------------------------------------------------------------
// Row softmax (2048 wide) -> P fp16
// ---------------------------------------------------------------------------
__global__ __launch_bounds__(256) void softmax_rows(const float* __restrict__ S,
                                                    __half* __restrict__ Ph)
{
    const size_t row = blockIdx.x;
    const float* p = S + row * (size_t)LSEQ;
    const int tid = threadIdx.x;

    float4 v0 = ((const float4*)p)[tid];
    float4 v1 = ((const float4*)p)[tid + 256];

    __shared__ float red[32];
    const int lane = tid & 31, warp = tid >> 5;

    float m = fmaxf(fmaxf(fmaxf(v0.x, v0.y), fmaxf(v0.z, v0.w)),
                    fmaxf(fmaxf(v1.x, v1.y), fmaxf(v1.z, v1.w)));
#pragma unroll
    for (int o = 16; o > 0; o >>= 1) m = fmaxf(m, __shfl_xor_sync(0xffffffffu, m, o));
    if (lane == 0) red[warp] = m;
    __syncthreads();
    if (warp == 0) {
        float mm = (lane < 8) ? red[lane] : -3.4e38f;
#pragma unroll
        for (int o = 4; o > 0; o >>= 1) mm = fmaxf(mm, __shfl_xor_sync(0xffffffffu, mm, o));
        if (lane == 0) red[0] = mm;
    }
    __syncthreads();
    m = red[0];
    __syncthreads();

    v0.x = __expf(v0.x - m); v0.y = __expf(v0.y - m);
    v0.z = __expf(v0.z - m); v0.w = __expf(v0.w - m);
    v1.x = __expf(v1.x - m); v1.y = __expf(v1.y - m);
    v1.z = __expf(v1.z - m); v1.w = __expf(v1.w - m);
    float s = v0.x + v0.y + v0.z + v0.w + v1.x + v1.y + v1.z + v1.w;
#pragma unroll
    for (int o = 16; o > 0; o >>= 1) s += __shfl_xor_sync(0xffffffffu, s, o);
    if (lane == 0) red[warp] = s;
    __syncthreads();
    if (warp == 0) {
        float ss = (lane < 8) ? red[lane] : 0.f;
#pragma unroll
        for (int o = 4; o > 0; o >>= 1) ss += __shfl_xor_sync(0xffffffffu, ss, o);
        if (lane == 0) red[0] = ss;
    }
    __syncthreads();
    const float inv = 1.0f / red[0];

    float a[8] = {v0.x*inv, v0.y*inv, v0.z*inv, v0.w*inv, v1.x*inv, v1.y*inv, v1.z*inv, v1.w*inv};
    const size_t o0 = row * (size_t)LSEQ + tid * 4;
    const size_t o1 = row * (size_t)LSEQ + (tid + 256) * 4;
    *reinterpret_cast<uint2*>(&Ph[o0]) = make_uint2(pk2h(a[0], a[1]), pk2h(a[2], a[3]));
    *reinterpret_cast<uint2*>(&Ph[o1]) = make_uint2(pk2h(a[4], a[5]), pk2h(a[6], a[7]));
}

// ---------------------------------------------------------------------------
extern "C" void kernel_launch(void* const* d_in, const int* in_sizes, int n_in,
                              void* d_out, int out_size)
{
    const float* x  = (const float*)d_in[0];
    const float* W1 = (const float*)d_in[1];
    const float* b1 = (const float*)d_in[2];
    const float* W2 = (const float*)d_in[3];
    const float* b2 = (const float*)d_in[4];
    float* out = (float*)d_out;

    __half *xh, *xl, *w1h, *w1l, *w2h, *w2l, *qh, *ql, *vh, *vl, *vth, *phh;
    float* S;
    cudaGetSymbolAddress((void**)&xh, g_xh);   cudaGetSymbolAddress((void**)&xl, g_xl);
    cudaGetSymbolAddress((void**)&w1h, g_w1h); cudaGetSymbolAddress((void**)&w1l, g_w1l);
    cudaGetSymbolAddress((void**)&w2h, g_w2h); cudaGetSymbolAddress((void**)&w2l, g_w2l);
    cudaGetSymbolAddress((void**)&qh, g_qh);   cudaGetSymbolAddress((void**)&ql, g_ql);
    cudaGetSymbolAddress((void**)&vh, g_vh);   cudaGetSymbolAddress((void**)&vl, g_vl);
    cudaGetSymbolAddress((void**)&vth, g_vth);
    cudaGetSymbolAddress((void**)&phh, g_ph);
    cudaGetSymbolAddress((void**)&S, g_S);

    cudaFuncSetAttribute(gemm_persist<true,  true,  3, true >, cudaFuncAttributeMaxDynamicSharedMemorySize, SMEM_TOTAL);
    cudaFuncSetAttribute(gemm_persist<false, false, 3, false>, cudaFuncAttributeMaxDynamicSharedMemorySize, SMEM_TOTAL);
    cudaFuncSetAttribute(gemm_persist<false, false, 1, false>, cudaFuncAttributeMaxDynamicSharedMemorySize, SMEM_TOTAL);

    const long long LD = (long long)LSEQ * DDIM;
    const long long LL = (long long)LSEQ * LSEQ;

    // 1. split fp32 -> fp16 hi/lo
    split_kernel<<<4096, 256>>>((const float4*)x,  (uint2*)xh,  (uint2*)xl,  8388608 / 4);
    split_kernel<<<1024, 256>>>((const float4*)W1, (uint2*)w1h, (uint2*)w1l, 1048576 / 4);
    split_kernel<<<1024, 256>>>((const float4*)W2, (uint2*)w2h, (uint2*)w2l, 1048576 / 4);

    // 2. Q = x@W1^T + b1 AND V = x@W2^T + b2, one persistent dual launch
    //    (M=8192, N=1024, K=1024; mt=64, nt=8, nz=1; 1024 tiles total)
    gemm_persist<true, true, 3, true><<<NPERSIST, 256, SMEM_TOTAL>>>(
        xh, xl, w1h, w1l, w2h, w2l, b1, b2,
        nullptr, qh, ql, vh, vl,
        DDIM, DDIM, DDIM, DDIM, 0, 0, 0,
        64, 8, 1);

    // 3. Vt = V^T per batch (hi only, for 1-pass stage 6)
    transpose_h<<<dim3(DDIM / 32, LSEQ / 32, BATCH), dim3(32, 8)>>>(vh, vth);

    // 4. S[b] = Q[b] @ V[b]^T  (M=2048, N=2048, K=1024, 3-pass; 1024 tiles)
    gemm_persist<false, false, 3, false><<<NPERSIST, 256, SMEM_TOTAL>>>(
        qh, ql, vh, vl, nullptr, nullptr, nullptr, nullptr,
        S, nullptr, nullptr, nullptr, nullptr,
        DDIM, DDIM, DDIM, LSEQ, LD, LD, LL,
        16, 16, BATCH);

    // 5. softmax -> P fp16
    softmax_rows<<<BATCH * LSEQ, 256>>>(S, phh);

    // 6. out[b] = P[b] @ Vt[b]^T  (M=2048, N=1024, K=2048, 1-pass; 512 tiles)
    gemm_persist<false, false, 1, false><<<NPERSIST, 256, SMEM_TOTAL>>>(
        phh, phh, vth, vth, nullptr, nullptr, nullptr, nullptr,
        out, nullptr, nullptr, nullptr, nullptr,
        LSEQ, LSEQ, LSEQ, DDIM, LL, LD, LD,
        16, 8, BATCH);
}